// round 4
// baseline (speedup 1.0000x reference)
#include <cuda_runtime.h>
#include <cuda_bf16.h>
#include <math.h>
#include <stdint.h>

#define BB 2
#define SS 2048
#define DIN 4096
#define NH 32
#define NKV 8
#define HD 64
#define QDIM (NH*HD)     // 2048
#define KVDIM (NKV*HD)   // 512
#define KVCAT (2*KVDIM)  // 1024 (fused K|V)
#define DOUT (DIN/2)     // 2048
#define MTOT (BB*SS)     // 4096

// ---------------- scratch (__device__ globals) ------------------------------
__device__ float g_q[MTOT*QDIM];
__device__ float g_kv[MTOT*KVCAT];         // fused: cols [0,512)=K, [512,1024)=V
__device__ float g_o[MTOT*QDIM];

__device__ __nv_bfloat16 g_hs_hi[MTOT*DIN];
__device__ __nv_bfloat16 g_hs_lo[MTOT*DIN];
__device__ __nv_bfloat16 g_ao_hi[MTOT*QDIM];
__device__ __nv_bfloat16 g_ao_lo[MTOT*QDIM];

__device__ __nv_bfloat16 g_wqT_hi[QDIM*DIN];
__device__ __nv_bfloat16 g_wqT_lo[QDIM*DIN];
__device__ __nv_bfloat16 g_wkvT_hi[KVCAT*DIN];   // rows 0..511 = Wk^T, 512..1023 = Wv^T
__device__ __nv_bfloat16 g_wkvT_lo[KVCAT*DIN];
__device__ __nv_bfloat16 g_woT_hi[DOUT*QDIM];
__device__ __nv_bfloat16 g_woT_lo[DOUT*QDIM];

// ---------------- helpers ----------------------------------------------------
__device__ __forceinline__ uint32_t smem_u32(const void* p) {
    uint32_t a;
    asm("{ .reg .u64 t; cvta.to.shared.u64 t, %1; cvt.u32.u64 %0, t; }" : "=r"(a) : "l"(p));
    return a;
}

#define LDSM4(r, addr)                                                           \
    asm volatile("ldmatrix.sync.aligned.m8n8.x4.shared.b16 {%0,%1,%2,%3}, [%4];" \
        : "=r"((r)[0]), "=r"((r)[1]), "=r"((r)[2]), "=r"((r)[3]) : "r"(addr))

#define MMA_BF16(d, a, b0, b1)                                                   \
    asm volatile("mma.sync.aligned.m16n8k16.row.col.f32.bf16.bf16.f32 "          \
        "{%0,%1,%2,%3}, {%4,%5,%6,%7}, {%8,%9}, {%0,%1,%2,%3};"                  \
        : "+f"((d)[0]), "+f"((d)[1]), "+f"((d)[2]), "+f"((d)[3])                 \
        : "r"((a)[0]), "r"((a)[1]), "r"((a)[2]), "r"((a)[3]), "r"(b0), "r"(b1))

#define CP_ASYNC16(dst, src)                                                     \
    asm volatile("cp.async.cg.shared.global [%0], [%1], 16;" :: "r"(dst), "l"(src) : "memory")
#define CP_COMMIT()  asm volatile("cp.async.commit_group;" ::: "memory")
#define CP_WAIT1()   asm volatile("cp.async.wait_group 1;" ::: "memory")

// ---------------- prep kernels ------------------------------------------------
__global__ void split_kernel(const float* __restrict__ x, __nv_bfloat16* __restrict__ hi,
                             __nv_bfloat16* __restrict__ lo, int n4) {
    int i = blockIdx.x * blockDim.x + threadIdx.x;
    if (i >= n4) return;
    float4 v = ((const float4*)x)[i];
    __nv_bfloat16 h[4], l[4];
    float vv[4] = {v.x, v.y, v.z, v.w};
    #pragma unroll
    for (int j = 0; j < 4; j++) {
        h[j] = __float2bfloat16(vv[j]);
        l[j] = __float2bfloat16(vv[j] - __bfloat162float(h[j]));
    }
    ((uint2*)hi)[i] = *(uint2*)h;
    ((uint2*)lo)[i] = *(uint2*)l;
}

// W: K x N row-major -> T (N x K) bf16 hi/lo
__global__ void transpose_split_kernel(const float* __restrict__ W,
                                       __nv_bfloat16* __restrict__ Th,
                                       __nv_bfloat16* __restrict__ Tl, int K, int N) {
    __shared__ float t[32][33];
    int k0 = blockIdx.y * 32, n0 = blockIdx.x * 32;
    int x = threadIdx.x, y = threadIdx.y;   // 32 x 8
    #pragma unroll
    for (int i = 0; i < 32; i += 8)
        t[y + i][x] = W[(size_t)(k0 + y + i) * N + n0 + x];
    __syncthreads();
    #pragma unroll
    for (int i = 0; i < 32; i += 8) {
        float v = t[x][y + i];
        __nv_bfloat16 h = __float2bfloat16(v);
        size_t idx = (size_t)(n0 + y + i) * K + k0 + x;
        Th[idx] = h;
        Tl[idx] = __float2bfloat16(v - __bfloat162float(h));
    }
}

// ---------------- split-bf16 HMMA GEMM, 3-stage pipeline -----------------------
#define AST 40
#define TILE_E (128*AST)
#define STAGE_E (4*TILE_E)
#define NSTAGE 3
#define GEMM_SMEM (NSTAGE * STAGE_E * 2)  // 122880 B

__device__ __forceinline__ void load_stage(
    uint32_t sbase_bytes, int tid, int bm, int bn, int k0, int K,
    const __nv_bfloat16* __restrict__ Ah, const __nv_bfloat16* __restrict__ Al,
    const __nv_bfloat16* __restrict__ Bh, const __nv_bfloat16* __restrict__ Bl)
{
    #pragma unroll
    for (int i = 0; i < 8; i++) {
        int cid = tid + i * 256;
        int arr = cid >> 9;
        int rem = cid & 511;
        int row = rem >> 2;
        int c16 = rem & 3;
        const __nv_bfloat16* g;
        if (arr == 0)      g = Ah + (size_t)(bm + row) * K + k0 + c16 * 8;
        else if (arr == 1) g = Al + (size_t)(bm + row) * K + k0 + c16 * 8;
        else if (arr == 2) g = Bh + (size_t)(bn + row) * K + k0 + c16 * 8;
        else               g = Bl + (size_t)(bn + row) * K + k0 + c16 * 8;
        uint32_t d = sbase_bytes + (uint32_t)(arr * TILE_E + row * AST + c16 * 8) * 2;
        CP_ASYNC16(d, g);
    }
    CP_COMMIT();
}

__global__ __launch_bounds__(256, 1)
void hmma_gemm(const __nv_bfloat16* __restrict__ Ah, const __nv_bfloat16* __restrict__ Al,
               const __nv_bfloat16* __restrict__ Bh, const __nv_bfloat16* __restrict__ Bl,
               float* __restrict__ C, int M, int N, int K)
{
    extern __shared__ __nv_bfloat16 sm[];
    const int tid = threadIdx.x;
    const int wid = tid >> 5;
    const int lane = tid & 31;
    const int bm = blockIdx.y * 128;
    const int bn = blockIdx.x * 128;
    const int wm = (wid & 3) * 32;
    const int wn = (wid >> 2) * 64;

    float acc[2][8][4];
    #pragma unroll
    for (int mt = 0; mt < 2; mt++)
        #pragma unroll
        for (int nt = 0; nt < 8; nt++)
            #pragma unroll
            for (int j = 0; j < 4; j++) acc[mt][nt][j] = 0.f;

    const uint32_t smb = smem_u32(sm);
    const int nch = K >> 5;

    load_stage(smb, tid, bm, bn, 0, K, Ah, Al, Bh, Bl);
    load_stage(smb + STAGE_E * 2, tid, bm, bn, 32, K, Ah, Al, Bh, Bl);

    int st = 0;        // stage of current chunk
    int pst = 2;       // stage to prefetch into
    for (int c = 0; c < nch; c++) {
        CP_WAIT1();          // chunk c resident (≤1 group pending)
        __syncthreads();     // all warps done with stage pst (chunk c-1's alias)

        if (c + 2 < nch)
            load_stage(smb + (uint32_t)pst * STAGE_E * 2, tid, bm, bn,
                       (c + 2) << 5, K, Ah, Al, Bh, Bl);

        uint32_t Ab  = smb + (uint32_t)st * STAGE_E * 2;
        uint32_t Alb = Ab + TILE_E * 2;
        uint32_t Bb  = Ab + 2 * TILE_E * 2;
        uint32_t Blb = Ab + 3 * TILE_E * 2;

        #pragma unroll
        for (int ks = 0; ks < 2; ks++) {
            uint32_t ah[2][4], al[2][4], bh[4][4], bl[4][4];
            #pragma unroll
            for (int mt = 0; mt < 2; mt++) {
                int row = wm + mt * 16 + (lane & 15);
                int col = ks * 16 + ((lane >> 4) << 3);
                uint32_t off = (uint32_t)(row * AST + col) * 2;
                LDSM4(ah[mt], Ab + off);
                LDSM4(al[mt], Alb + off);
            }
            #pragma unroll
            for (int p = 0; p < 4; p++) {
                int row = wn + p * 16 + (lane & 7) + ((lane >> 4) << 3);
                int col = ks * 16 + (((lane >> 3) & 1) << 3);
                uint32_t off = (uint32_t)(row * AST + col) * 2;
                LDSM4(bh[p], Bb + off);
                LDSM4(bl[p], Blb + off);
            }
            #pragma unroll
            for (int mt = 0; mt < 2; mt++) {
                #pragma unroll
                for (int nt = 0; nt < 8; nt++) {
                    uint32_t b0h = bh[nt >> 1][(nt & 1) * 2];
                    uint32_t b1h = bh[nt >> 1][(nt & 1) * 2 + 1];
                    uint32_t b0l = bl[nt >> 1][(nt & 1) * 2];
                    uint32_t b1l = bl[nt >> 1][(nt & 1) * 2 + 1];
                    MMA_BF16(acc[mt][nt], ah[mt], b0h, b1h);
                    MMA_BF16(acc[mt][nt], ah[mt], b0l, b1l);
                    MMA_BF16(acc[mt][nt], al[mt], b0h, b1h);
                }
            }
        }
        st = (st == 2) ? 0 : st + 1;
        pst = (pst == 2) ? 0 : pst + 1;
    }

    #pragma unroll
    for (int mt = 0; mt < 2; mt++) {
        #pragma unroll
        for (int nt = 0; nt < 8; nt++) {
            int r0  = bm + wm + mt * 16 + (lane >> 2);
            int col = bn + wn + nt * 8 + (lane & 3) * 2;
            *(float2*)&C[(size_t)r0 * N + col] =
                make_float2(acc[mt][nt][0], acc[mt][nt][1]);
            *(float2*)&C[(size_t)(r0 + 8) * N + col] =
                make_float2(acc[mt][nt][2], acc[mt][nt][3]);
        }
    }
}

// ---------------- RoPE (stride-aware for fused KV buffer) ---------------------
__global__ void rope_kernel(float* __restrict__ buf, const int* __restrict__ pos_ids,
                            int stride, int nheads)
{
    const int half = nheads * 32;
    int idx = blockIdx.x * blockDim.x + threadIdx.x;
    int total = BB * SS * half;
    if (idx >= total) return;
    int row = idx / half;
    int pr  = idx - row * half;
    int h  = pr >> 5;
    int jp = pr & 31;
    float pos = (float)pos_ids[row];
    float inv = exp2f(-(float)jp * (13.287712379549449f / 32.0f));
    float ang = pos * inv;
    float s, c;
    sincosf(ang, &s, &c);
    float* p1 = buf + (size_t)row * stride + h * 64 + jp;
    float* p2 = p1 + 32;
    float x1 = *p1, x2 = *p2;
    *p1 = x1 * c - x2 * s;
    *p2 = x2 * c + x1 * s;
}

// ---------------- flash attention (fp32; fused-KV indexing) --------------------
#define PAD 68
__global__ __launch_bounds__(256, 3)
void attn_kernel(const float* __restrict__ q, const float* __restrict__ kv,
                 float* __restrict__ o)
{
    extern __shared__ float smf[];
    float* q_s     = smf;
    float* k_sT    = q_s  + 64 * PAD;
    float* v_s     = k_sT + 64 * PAD;
    float* s_s     = v_s  + 64 * PAD;
    float* scale_s = s_s  + 64 * PAD;
    float* l_s     = scale_s + 64;

    const int qt = blockIdx.x;
    const int h  = blockIdx.y;
    const int b  = blockIdx.z;
    const int kvh = h >> 2;

    const int t  = threadIdx.x;
    const int r  = t >> 2;
    const int c0 = (t & 3) << 4;

    const float qscale = 0.125f;
    #pragma unroll
    for (int rep = 0; rep < 4; rep++) {
        int idx = t + rep * 256;
        int i  = idx >> 4;
        int d4 = (idx & 15) << 2;
        float4 qv = *(const float4*)&q[((size_t)(b * SS + qt * 64 + i)) * QDIM + h * HD + d4];
        float* dst = &q_s[i * PAD + d4];
        dst[0] = qv.x * qscale; dst[1] = qv.y * qscale;
        dst[2] = qv.z * qscale; dst[3] = qv.w * qscale;
    }

    float acc[16];
    #pragma unroll
    for (int i = 0; i < 16; i++) acc[i] = 0.f;
    float m_r = -1e30f, l_r = 0.f;

    const int n_kt = qt + 1;
    const int qi = qt * 64 + r;

    for (int kt = 0; kt < n_kt; kt++) {
        __syncthreads();

        #pragma unroll
        for (int rep = 0; rep < 4; rep++) {
            int idx = t + rep * 256;
            int c  = idx >> 4;
            int d4 = (idx & 15) << 2;
            size_t base = ((size_t)(b * SS + kt * 64 + c)) * KVCAT + kvh * HD + d4;
            float4 kvv = *(const float4*)&kv[base];
            k_sT[(d4 + 0) * PAD + c] = kvv.x;
            k_sT[(d4 + 1) * PAD + c] = kvv.y;
            k_sT[(d4 + 2) * PAD + c] = kvv.z;
            k_sT[(d4 + 3) * PAD + c] = kvv.w;
            *(float4*)&v_s[c * PAD + d4] = *(const float4*)&kv[base + KVDIM];
        }
        __syncthreads();

        float sacc[16];
        #pragma unroll
        for (int i = 0; i < 16; i++) sacc[i] = 0.f;

        #pragma unroll 8
        for (int d = 0; d < 64; d++) {
            float qv = q_s[r * PAD + d];
            const float4* kp = (const float4*)&k_sT[d * PAD + c0];
            float4 k0 = kp[0], k1 = kp[1], k2 = kp[2], k3 = kp[3];
            sacc[0]  += qv * k0.x; sacc[1]  += qv * k0.y; sacc[2]  += qv * k0.z; sacc[3]  += qv * k0.w;
            sacc[4]  += qv * k1.x; sacc[5]  += qv * k1.y; sacc[6]  += qv * k1.z; sacc[7]  += qv * k1.w;
            sacc[8]  += qv * k2.x; sacc[9]  += qv * k2.y; sacc[10] += qv * k2.z; sacc[11] += qv * k2.w;
            sacc[12] += qv * k3.x; sacc[13] += qv * k3.y; sacc[14] += qv * k3.z; sacc[15] += qv * k3.w;
        }
        #pragma unroll
        for (int i = 0; i < 16; i++) {
            int kj = kt * 64 + c0 + i;
            s_s[r * PAD + c0 + i] = (kj <= qi) ? sacc[i] : -1e30f;
        }
        __syncthreads();

        if (t < 64) {
            float* srow = &s_s[t * PAD];
            float mx = -1e30f;
            #pragma unroll 8
            for (int c = 0; c < 64; c++) mx = fmaxf(mx, srow[c]);
            float new_m = fmaxf(m_r, mx);
            float sum = 0.f;
            #pragma unroll 8
            for (int c = 0; c < 64; c++) {
                float p = __expf(srow[c] - new_m);
                srow[c] = p;
                sum += p;
            }
            float sc = __expf(m_r - new_m);
            l_r = l_r * sc + sum;
            m_r = new_m;
            scale_s[t] = sc;
        }
        __syncthreads();

        float sc = scale_s[r];
        #pragma unroll
        for (int i = 0; i < 16; i++) acc[i] *= sc;

        #pragma unroll 8
        for (int c = 0; c < 64; c++) {
            float p = s_s[r * PAD + c];
            const float4* vp = (const float4*)&v_s[c * PAD + c0];
            float4 v0 = vp[0], v1 = vp[1], v2 = vp[2], v3 = vp[3];
            acc[0]  += p * v0.x; acc[1]  += p * v0.y; acc[2]  += p * v0.z; acc[3]  += p * v0.w;
            acc[4]  += p * v1.x; acc[5]  += p * v1.y; acc[6]  += p * v1.z; acc[7]  += p * v1.w;
            acc[8]  += p * v2.x; acc[9]  += p * v2.y; acc[10] += p * v2.z; acc[11] += p * v2.w;
            acc[12] += p * v3.x; acc[13] += p * v3.y; acc[14] += p * v3.z; acc[15] += p * v3.w;
        }
    }

    if (t < 64) l_s[t] = l_r;
    __syncthreads();

    float inv_l = 1.0f / l_s[r];
    float* obase = o + ((size_t)(b * SS + qt * 64 + r)) * QDIM + h * HD + c0;
    #pragma unroll
    for (int j = 0; j < 4; j++) {
        *(float4*)&obase[4 * j] = make_float4(acc[4 * j + 0] * inv_l,
                                              acc[4 * j + 1] * inv_l,
                                              acc[4 * j + 2] * inv_l,
                                              acc[4 * j + 3] * inv_l);
    }
}

// ---------------------------------------------------------------------------
extern "C" void kernel_launch(void* const* d_in, const int* in_sizes, int n_in,
                              void* d_out, int out_size)
{
    (void)in_sizes; (void)n_in; (void)out_size;
    const float* hs  = (const float*)d_in[0];
    const int*   pos = (const int*)d_in[2];
    const float* Wq  = (const float*)d_in[3];
    const float* Wk  = (const float*)d_in[4];
    const float* Wv  = (const float*)d_in[5];
    const float* Wo  = (const float*)d_in[6];
    float* out = (float*)d_out;

    float *qb, *kvb, *ob;
    cudaGetSymbolAddress((void**)&qb, g_q);
    cudaGetSymbolAddress((void**)&kvb, g_kv);
    cudaGetSymbolAddress((void**)&ob, g_o);

    __nv_bfloat16 *hsh, *hsl, *aoh, *aol;
    __nv_bfloat16 *wqh, *wql, *wkvh, *wkvl, *woh, *wol;
    cudaGetSymbolAddress((void**)&hsh, g_hs_hi);
    cudaGetSymbolAddress((void**)&hsl, g_hs_lo);
    cudaGetSymbolAddress((void**)&aoh, g_ao_hi);
    cudaGetSymbolAddress((void**)&aol, g_ao_lo);
    cudaGetSymbolAddress((void**)&wqh, g_wqT_hi);
    cudaGetSymbolAddress((void**)&wql, g_wqT_lo);
    cudaGetSymbolAddress((void**)&wkvh, g_wkvT_hi);
    cudaGetSymbolAddress((void**)&wkvl, g_wkvT_lo);
    cudaGetSymbolAddress((void**)&woh, g_woT_hi);
    cudaGetSymbolAddress((void**)&wol, g_woT_lo);

    const int M = MTOT;

    cudaFuncSetAttribute(hmma_gemm, cudaFuncAttributeMaxDynamicSharedMemorySize, GEMM_SMEM);

    // Launch order chosen so launch #5 (ncu's capture point) is the Q GEMM.
    split_kernel<<<(M * DIN / 4 + 255) / 256, 256>>>(hs, hsh, hsl, M * DIN / 4);          // 1
    transpose_split_kernel<<<dim3(QDIM / 32,  DIN / 32), dim3(32, 8)>>>(Wq, wqh, wql, DIN, QDIM);   // 2
    transpose_split_kernel<<<dim3(KVDIM / 32, DIN / 32), dim3(32, 8)>>>(Wk, wkvh, wkvl, DIN, KVDIM); // 3
    transpose_split_kernel<<<dim3(KVDIM / 32, DIN / 32), dim3(32, 8)>>>(
        Wv, wkvh + (size_t)KVDIM * DIN, wkvl + (size_t)KVDIM * DIN, DIN, KVDIM);           // 4
    hmma_gemm<<<dim3(QDIM / 128, M / 128), 256, GEMM_SMEM>>>(hsh, hsl, wqh, wql, qb, M, QDIM, DIN); // 5 (profiled)
    transpose_split_kernel<<<dim3(DOUT / 32, QDIM / 32), dim3(32, 8)>>>(Wo, woh, wol, QDIM, DOUT);  // 6
    hmma_gemm<<<dim3(KVCAT / 128, M / 128), 256, GEMM_SMEM>>>(hsh, hsl, wkvh, wkvl, kvb, M, KVCAT, DIN); // 7

    rope_kernel<<<(M * NH * 32 + 255) / 256, 256>>>(qb, pos, QDIM, NH);     // 8
    rope_kernel<<<(M * NKV * 32 + 255) / 256, 256>>>(kvb, pos, KVCAT, NKV); // 9

    const int smem = (4 * 64 * PAD + 128) * (int)sizeof(float);
    cudaFuncSetAttribute(attn_kernel, cudaFuncAttributeMaxDynamicSharedMemorySize, smem);
    attn_kernel<<<dim3(SS / 64, NH, BB), 256, smem>>>(qb, kvb, ob);          // 10

    split_kernel<<<(M * QDIM / 4 + 255) / 256, 256>>>(ob, aoh, aol, M * QDIM / 4);  // 11
    hmma_gemm<<<dim3(DOUT / 128, M / 128), 256, GEMM_SMEM>>>(aoh, aol, woh, wol, out, M, DOUT, QDIM); // 12
}

// round 5
// speedup vs baseline: 3.1912x; 3.1912x over previous
#include <cuda_runtime.h>
#include <cuda_bf16.h>
#include <math.h>
#include <stdint.h>

#define BB 2
#define SS 2048
#define DIN 4096
#define NH 32
#define NKV 8
#define HD 64
#define QDIM 2048
#define KVDIM 512
#define QKVN 3072            // fused Q|K|V projection width
#define DOUT 2048
#define MTOT 4096

// ---------------- scratch (__device__ globals) ------------------------------
__device__ float g_qkv[MTOT*QKVN];                 // fp32 QKV projection output
__device__ __nv_bfloat16 g_hs_hi[MTOT*DIN];
__device__ __nv_bfloat16 g_hs_lo[MTOT*DIN];
__device__ __nv_bfloat16 g_qh[MTOT*QDIM];          // roped, pre-scaled Q hi/lo
__device__ __nv_bfloat16 g_ql[MTOT*QDIM];
__device__ __nv_bfloat16 g_kh[MTOT*KVDIM];         // roped K hi/lo
__device__ __nv_bfloat16 g_kl[MTOT*KVDIM];
__device__ __nv_bfloat16 g_vth[BB*NKV*HD*SS];      // V transposed [b][kvh][d][tok] hi/lo
__device__ __nv_bfloat16 g_vtl[BB*NKV*HD*SS];
__device__ __nv_bfloat16 g_aoh[MTOT*QDIM];         // attention out hi/lo
__device__ __nv_bfloat16 g_aol[MTOT*QDIM];
__device__ __nv_bfloat16 g_wqkvT_hi[QKVN*DIN];
__device__ __nv_bfloat16 g_wqkvT_lo[QKVN*DIN];
__device__ __nv_bfloat16 g_woT_hi[DOUT*QDIM];
__device__ __nv_bfloat16 g_woT_lo[DOUT*QDIM];

// ---------------- helpers ----------------------------------------------------
__device__ __forceinline__ uint32_t smem_u32(const void* p) {
    uint32_t a;
    asm("{ .reg .u64 t; cvta.to.shared.u64 t, %1; cvt.u32.u64 %0, t; }" : "=r"(a) : "l"(p));
    return a;
}

#define LDSM4(r, addr)                                                           \
    asm volatile("ldmatrix.sync.aligned.m8n8.x4.shared.b16 {%0,%1,%2,%3}, [%4];" \
        : "=r"((r)[0]), "=r"((r)[1]), "=r"((r)[2]), "=r"((r)[3]) : "r"(addr))

#define MMA_BF16(d, a, b0, b1)                                                   \
    asm volatile("mma.sync.aligned.m16n8k16.row.col.f32.bf16.bf16.f32 "          \
        "{%0,%1,%2,%3}, {%4,%5,%6,%7}, {%8,%9}, {%0,%1,%2,%3};"                  \
        : "+f"((d)[0]), "+f"((d)[1]), "+f"((d)[2]), "+f"((d)[3])                 \
        : "r"((a)[0]), "r"((a)[1]), "r"((a)[2]), "r"((a)[3]), "r"(b0), "r"(b1))

#define CP_ASYNC16(dst, src)                                                     \
    asm volatile("cp.async.cg.shared.global [%0], [%1], 16;" :: "r"(dst), "l"(src) : "memory")
#define CP_COMMIT()  asm volatile("cp.async.commit_group;" ::: "memory")
#define CP_WAIT1()   asm volatile("cp.async.wait_group 1;" ::: "memory")
#define CP_WAIT0()   asm volatile("cp.async.wait_group 0;" ::: "memory")

// pack two fp32 -> bf16x2 (lo in low half)
__device__ __forceinline__ uint32_t pack_bf16(float lo, float hi) {
    uint32_t r;
    asm("cvt.rn.bf16x2.f32 %0, %1, %2;" : "=r"(r) : "f"(hi), "f"(lo));
    return r;
}
__device__ __forceinline__ float bfr(float x) {
    return __bfloat162float(__float2bfloat16(x));
}

// fast exp on the FMA pipe: exp(x) = 2^(x*log2e), x <= 0
__device__ __forceinline__ float fast_exp(float x) {
    float t = fmaxf(x * 1.4426950408889634f, -126.0f);
    float fi = floorf(t);
    float f = t - fi;
    float p = 1.54035304e-4f;
    p = fmaf(p, f, 1.33335581e-3f);
    p = fmaf(p, f, 9.61812911e-3f);
    p = fmaf(p, f, 5.55041087e-2f);
    p = fmaf(p, f, 2.40226507e-1f);
    p = fmaf(p, f, 6.93147181e-1f);
    p = fmaf(p, f, 1.0f);
    return p * __uint_as_float(((uint32_t)((int)fi + 127)) << 23);
}

// ---------------- prep kernels ------------------------------------------------
__global__ void split_kernel(const float* __restrict__ x, __nv_bfloat16* __restrict__ hi,
                             __nv_bfloat16* __restrict__ lo, int n4) {
    int i = blockIdx.x * blockDim.x + threadIdx.x;
    if (i >= n4) return;
    float4 v = ((const float4*)x)[i];
    __nv_bfloat16 h[4], l[4];
    float vv[4] = {v.x, v.y, v.z, v.w};
    #pragma unroll
    for (int j = 0; j < 4; j++) {
        h[j] = __float2bfloat16(vv[j]);
        l[j] = __float2bfloat16(vv[j] - __bfloat162float(h[j]));
    }
    ((uint2*)hi)[i] = *(uint2*)h;
    ((uint2*)lo)[i] = *(uint2*)l;
}

// fused transpose+split of Wq|Wk|Wv into one (3072 x 4096) hi/lo buffer
__global__ void transpose_split_qkv(const float* __restrict__ Wq, const float* __restrict__ Wk,
                                    const float* __restrict__ Wv,
                                    __nv_bfloat16* __restrict__ Th, __nv_bfloat16* __restrict__ Tl) {
    __shared__ float t[32][33];
    int n0 = blockIdx.x * 32;   // 0..3071
    int k0 = blockIdx.y * 32;   // 0..4095
    const float* W; int srcN, sn0;
    if (n0 < QDIM)              { W = Wq; srcN = QDIM;  sn0 = n0; }
    else if (n0 < QDIM + KVDIM) { W = Wk; srcN = KVDIM; sn0 = n0 - QDIM; }
    else                        { W = Wv; srcN = KVDIM; sn0 = n0 - QDIM - KVDIM; }
    int x = threadIdx.x, y = threadIdx.y;
    #pragma unroll
    for (int i = 0; i < 32; i += 8)
        t[y + i][x] = W[(size_t)(k0 + y + i) * srcN + sn0 + x];
    __syncthreads();
    #pragma unroll
    for (int i = 0; i < 32; i += 8) {
        float v = t[x][y + i];
        float h = bfr(v);
        size_t idx = (size_t)(n0 + y + i) * DIN + k0 + x;
        Th[idx] = __float2bfloat16(h);
        Tl[idx] = __float2bfloat16(v - h);
    }
}

// generic transpose+split (for Wo)
__global__ void transpose_split_kernel(const float* __restrict__ W,
                                       __nv_bfloat16* __restrict__ Th,
                                       __nv_bfloat16* __restrict__ Tl, int K, int N) {
    __shared__ float t[32][33];
    int k0 = blockIdx.y * 32, n0 = blockIdx.x * 32;
    int x = threadIdx.x, y = threadIdx.y;
    #pragma unroll
    for (int i = 0; i < 32; i += 8)
        t[y + i][x] = W[(size_t)(k0 + y + i) * N + n0 + x];
    __syncthreads();
    #pragma unroll
    for (int i = 0; i < 32; i += 8) {
        float v = t[x][y + i];
        float h = bfr(v);
        size_t idx = (size_t)(n0 + y + i) * K + k0 + x;
        Th[idx] = __float2bfloat16(h);
        Tl[idx] = __float2bfloat16(v - h);
    }
}

// RoPE + bf16 hi/lo split for Q (scaled by 0.125) and K, from fused QKV buffer
__global__ void rope_split(const float* __restrict__ qkv, const int* __restrict__ pos,
                           __nv_bfloat16* __restrict__ qh, __nv_bfloat16* __restrict__ ql,
                           __nv_bfloat16* __restrict__ kh, __nv_bfloat16* __restrict__ kl) {
    int idx = blockIdx.x * blockDim.x + threadIdx.x;
    const int per_row = (NH + NKV) * 32;   // 1280
    if (idx >= MTOT * per_row) return;
    int row = idx / per_row;
    int r   = idx - row * per_row;
    int isq = r < NH * 32;
    int h   = (isq ? r : r - NH * 32) >> 5;
    int jp  = r & 31;
    float pf = (float)pos[row];
    float inv = exp2f(-(float)jp * (13.287712379549449f / 32.0f));
    float ang = pf * inv;
    float s, c;
    sincosf(ang, &s, &c);
    const float* src = qkv + (size_t)row * QKVN + (isq ? 0 : QDIM) + h * 64 + jp;
    float x1 = src[0], x2 = src[32];
    float y1 = x1 * c - x2 * s;
    float y2 = x2 * c + x1 * s;
    if (isq) { y1 *= 0.125f; y2 *= 0.125f; }
    __nv_bfloat16* oh = isq ? qh : kh;
    __nv_bfloat16* ol = isq ? ql : kl;
    size_t o = (size_t)row * (isq ? QDIM : KVDIM) + h * 64 + jp;
    float h1 = bfr(y1), h2 = bfr(y2);
    oh[o]      = __float2bfloat16(h1); ol[o]      = __float2bfloat16(y1 - h1);
    oh[o + 32] = __float2bfloat16(h2); ol[o + 32] = __float2bfloat16(y2 - h2);
}

// V: split + transpose into [b][kvh][d][tok] hi/lo
__global__ void vsplit_t(const float* __restrict__ qkv,
                         __nv_bfloat16* __restrict__ vth, __nv_bfloat16* __restrict__ vtl) {
    __shared__ float t[32][33];
    int bh = blockIdx.z;
    int b = bh >> 3, kvh = bh & 7;
    int t0 = blockIdx.x * 32, d0 = blockIdx.y * 32;
    int x = threadIdx.x, y = threadIdx.y;
    #pragma unroll
    for (int i = 0; i < 32; i += 8)
        t[y + i][x] = qkv[(size_t)(b * SS + t0 + y + i) * QKVN + QDIM + KVDIM + kvh * 64 + d0 + x];
    __syncthreads();
    #pragma unroll
    for (int i = 0; i < 32; i += 8) {
        float v = t[x][y + i];
        float h = bfr(v);
        size_t o = ((size_t)((b * NKV + kvh) * HD + d0 + y + i)) * SS + t0 + x;
        vth[o] = __float2bfloat16(h);
        vtl[o] = __float2bfloat16(v - h);
    }
}

// ---------------- split-bf16 HMMA GEMM (3-stage, unchanged core) ----------------
#define AST 40
#define TILE_E (128*AST)
#define STAGE_E (4*TILE_E)
#define NSTAGE 3
#define GEMM_SMEM (NSTAGE * STAGE_E * 2)

__device__ __forceinline__ void load_stage(
    uint32_t sbase_bytes, int tid, int bm, int bn, int k0, int K,
    const __nv_bfloat16* __restrict__ Ah, const __nv_bfloat16* __restrict__ Al,
    const __nv_bfloat16* __restrict__ Bh, const __nv_bfloat16* __restrict__ Bl)
{
    #pragma unroll
    for (int i = 0; i < 8; i++) {
        int cid = tid + i * 256;
        int arr = cid >> 9;
        int rem = cid & 511;
        int row = rem >> 2;
        int c16 = rem & 3;
        const __nv_bfloat16* g;
        if (arr == 0)      g = Ah + (size_t)(bm + row) * K + k0 + c16 * 8;
        else if (arr == 1) g = Al + (size_t)(bm + row) * K + k0 + c16 * 8;
        else if (arr == 2) g = Bh + (size_t)(bn + row) * K + k0 + c16 * 8;
        else               g = Bl + (size_t)(bn + row) * K + k0 + c16 * 8;
        uint32_t d = sbase_bytes + (uint32_t)(arr * TILE_E + row * AST + c16 * 8) * 2;
        CP_ASYNC16(d, g);
    }
    CP_COMMIT();
}

__global__ __launch_bounds__(256, 1)
void hmma_gemm(const __nv_bfloat16* __restrict__ Ah, const __nv_bfloat16* __restrict__ Al,
               const __nv_bfloat16* __restrict__ Bh, const __nv_bfloat16* __restrict__ Bl,
               float* __restrict__ C, int M, int N, int K)
{
    extern __shared__ __nv_bfloat16 sm[];
    const int tid = threadIdx.x;
    const int wid = tid >> 5;
    const int lane = tid & 31;
    const int bm = blockIdx.y * 128;
    const int bn = blockIdx.x * 128;
    const int wm = (wid & 3) * 32;
    const int wn = (wid >> 2) * 64;

    float acc[2][8][4];
    #pragma unroll
    for (int mt = 0; mt < 2; mt++)
        #pragma unroll
        for (int nt = 0; nt < 8; nt++)
            #pragma unroll
            for (int j = 0; j < 4; j++) acc[mt][nt][j] = 0.f;

    const uint32_t smb = smem_u32(sm);
    const int nch = K >> 5;

    load_stage(smb, tid, bm, bn, 0, K, Ah, Al, Bh, Bl);
    load_stage(smb + STAGE_E * 2, tid, bm, bn, 32, K, Ah, Al, Bh, Bl);

    int st = 0, pst = 2;
    for (int c = 0; c < nch; c++) {
        CP_WAIT1();
        __syncthreads();

        if (c + 2 < nch)
            load_stage(smb + (uint32_t)pst * STAGE_E * 2, tid, bm, bn,
                       (c + 2) << 5, K, Ah, Al, Bh, Bl);

        uint32_t Ab  = smb + (uint32_t)st * STAGE_E * 2;
        uint32_t Alb = Ab + TILE_E * 2;
        uint32_t Bb  = Ab + 2 * TILE_E * 2;
        uint32_t Blb = Ab + 3 * TILE_E * 2;

        #pragma unroll
        for (int ks = 0; ks < 2; ks++) {
            uint32_t ah[2][4], al[2][4], bh[4][4], bl[4][4];
            #pragma unroll
            for (int mt = 0; mt < 2; mt++) {
                int row = wm + mt * 16 + (lane & 15);
                int col = ks * 16 + ((lane >> 4) << 3);
                uint32_t off = (uint32_t)(row * AST + col) * 2;
                LDSM4(ah[mt], Ab + off);
                LDSM4(al[mt], Alb + off);
            }
            #pragma unroll
            for (int p = 0; p < 4; p++) {
                int row = wn + p * 16 + (lane & 7) + ((lane >> 4) << 3);
                int col = ks * 16 + (((lane >> 3) & 1) << 3);
                uint32_t off = (uint32_t)(row * AST + col) * 2;
                LDSM4(bh[p], Bb + off);
                LDSM4(bl[p], Blb + off);
            }
            #pragma unroll
            for (int mt = 0; mt < 2; mt++) {
                #pragma unroll
                for (int nt = 0; nt < 8; nt++) {
                    uint32_t b0h = bh[nt >> 1][(nt & 1) * 2];
                    uint32_t b1h = bh[nt >> 1][(nt & 1) * 2 + 1];
                    uint32_t b0l = bl[nt >> 1][(nt & 1) * 2];
                    uint32_t b1l = bl[nt >> 1][(nt & 1) * 2 + 1];
                    MMA_BF16(acc[mt][nt], ah[mt], b0h, b1h);
                    MMA_BF16(acc[mt][nt], ah[mt], b0l, b1l);
                    MMA_BF16(acc[mt][nt], al[mt], b0h, b1h);
                }
            }
        }
        st = (st == 2) ? 0 : st + 1;
        pst = (pst == 2) ? 0 : pst + 1;
    }

    #pragma unroll
    for (int mt = 0; mt < 2; mt++) {
        #pragma unroll
        for (int nt = 0; nt < 8; nt++) {
            int r0  = bm + wm + mt * 16 + (lane >> 2);
            int col = bn + wn + nt * 8 + (lane & 3) * 2;
            *(float2*)&C[(size_t)r0 * N + col] =
                make_float2(acc[mt][nt][0], acc[mt][nt][1]);
            *(float2*)&C[(size_t)(r0 + 8) * N + col] =
                make_float2(acc[mt][nt][2], acc[mt][nt][3]);
        }
    }
}

// ---------------- HMMA flash attention (split-bf16, GQA-shared KV) -------------
// CTA: (qt, kvh, b). M = 256 rows = 4 q-heads x 64 tokens. 8 warps, 32 rows each.
#define QST 72
#define ATT_Q_E  (256*QST)          // per hi/lo array
#define ATT_KV_E (64*QST)
#define ATT_SMEM ((2*ATT_Q_E + 4*ATT_KV_E) * 2)  // 110592 bytes

__global__ __launch_bounds__(256, 1)
void attn_hmma(const __nv_bfloat16* __restrict__ qh, const __nv_bfloat16* __restrict__ ql,
               const __nv_bfloat16* __restrict__ kh, const __nv_bfloat16* __restrict__ kl,
               const __nv_bfloat16* __restrict__ vth, const __nv_bfloat16* __restrict__ vtl,
               __nv_bfloat16* __restrict__ aoh, __nv_bfloat16* __restrict__ aol)
{
    extern __shared__ __nv_bfloat16 smatt[];
    const int qt  = gridDim.x - 1 - blockIdx.x;   // big tiles first
    const int kvh = blockIdx.y;
    const int b   = blockIdx.z;
    const int tid = threadIdx.x, wid = tid >> 5, lane = tid & 31;

    const uint32_t smb  = smem_u32(smatt);
    const uint32_t Qh_o = smb;
    const uint32_t Ql_o = smb + ATT_Q_E * 2;
    const uint32_t Kh_o = smb + 2 * ATT_Q_E * 2;
    const uint32_t Kl_o = Kh_o + ATT_KV_E * 2;
    const uint32_t Vh_o = Kl_o + ATT_KV_E * 2;
    const uint32_t Vl_o = Vh_o + ATT_KV_E * 2;

    // ---- load Q tile (256 rows x 64 cols, hi+lo): 4096 x 16B
    #pragma unroll
    for (int it = 0; it < 16; it++) {
        int cid = tid + it * 256;
        int arr = cid >> 11;
        int rem = cid & 2047;
        int row = rem >> 3;
        int c   = rem & 7;
        const __nv_bfloat16* src = (arr ? ql : qh)
            + (size_t)(b * SS + qt * 64 + (row & 63)) * QDIM
            + (kvh * 4 + (row >> 6)) * 64 + c * 8;
        uint32_t dst = (arr ? Ql_o : Qh_o) + (uint32_t)(row * QST + c * 8) * 2;
        CP_ASYNC16(dst, src);
    }
    CP_COMMIT();

    float m_r[2][2], l_r[2][2], oacc[2][8][4];
    #pragma unroll
    for (int mt = 0; mt < 2; mt++) {
        m_r[mt][0] = -1e30f; m_r[mt][1] = -1e30f;
        l_r[mt][0] = 0.f;    l_r[mt][1] = 0.f;
        #pragma unroll
        for (int nt = 0; nt < 8; nt++)
            #pragma unroll
            for (int j = 0; j < 4; j++) oacc[mt][nt][j] = 0.f;
    }

    const int wrow  = wid * 32;        // M-row base (stacked heads)
    const int hloc  = wid >> 1;        // q head within group
    const int rtile = (wid & 1) * 32;  // token row base within 64-tile

    for (int kt = 0; kt <= qt; kt++) {
        // ---- load K/V tiles (hi+lo): 2048 x 16B
        #pragma unroll
        for (int it = 0; it < 8; it++) {
            int cid = tid + it * 256;
            int arr = cid >> 9;
            int rem = cid & 511;
            int row = rem >> 3;
            int c   = rem & 7;
            const __nv_bfloat16* src;
            uint32_t dstb;
            if (arr == 0)      { src = kh  + (size_t)(b * SS + kt * 64 + row) * KVDIM + kvh * 64 + c * 8; dstb = Kh_o; }
            else if (arr == 1) { src = kl  + (size_t)(b * SS + kt * 64 + row) * KVDIM + kvh * 64 + c * 8; dstb = Kl_o; }
            else if (arr == 2) { src = vth + (size_t)((b * NKV + kvh) * HD + row) * SS + kt * 64 + c * 8; dstb = Vh_o; }
            else               { src = vtl + (size_t)((b * NKV + kvh) * HD + row) * SS + kt * 64 + c * 8; dstb = Vl_o; }
            CP_ASYNC16(dstb + (uint32_t)(row * QST + c * 8) * 2, src);
        }
        CP_COMMIT();
        CP_WAIT0();
        __syncthreads();

        // ---- S = Q K^T (3-term split)
        float sacc[2][8][4];
        #pragma unroll
        for (int mt = 0; mt < 2; mt++)
            #pragma unroll
            for (int nt = 0; nt < 8; nt++)
                #pragma unroll
                for (int j = 0; j < 4; j++) sacc[mt][nt][j] = 0.f;

        #pragma unroll
        for (int ks = 0; ks < 4; ks++) {
            uint32_t qa_h[2][4], qa_l[2][4], kb_h[4][4], kb_l[4][4];
            #pragma unroll
            for (int mt = 0; mt < 2; mt++) {
                int row = wrow + mt * 16 + (lane & 15);
                int col = ks * 16 + ((lane >> 4) << 3);
                uint32_t off = (uint32_t)(row * QST + col) * 2;
                LDSM4(qa_h[mt], Qh_o + off);
                LDSM4(qa_l[mt], Ql_o + off);
            }
            #pragma unroll
            for (int p = 0; p < 4; p++) {
                int row = p * 16 + (lane & 7) + ((lane >> 4) << 3);
                int col = ks * 16 + (((lane >> 3) & 1) << 3);
                uint32_t off = (uint32_t)(row * QST + col) * 2;
                LDSM4(kb_h[p], Kh_o + off);
                LDSM4(kb_l[p], Kl_o + off);
            }
            #pragma unroll
            for (int mt = 0; mt < 2; mt++) {
                #pragma unroll
                for (int nt = 0; nt < 8; nt++) {
                    uint32_t b0h = kb_h[nt >> 1][(nt & 1) * 2];
                    uint32_t b1h = kb_h[nt >> 1][(nt & 1) * 2 + 1];
                    uint32_t b0l = kb_l[nt >> 1][(nt & 1) * 2];
                    uint32_t b1l = kb_l[nt >> 1][(nt & 1) * 2 + 1];
                    MMA_BF16(sacc[mt][nt], qa_h[mt], b0h, b1h);
                    MMA_BF16(sacc[mt][nt], qa_h[mt], b0l, b1l);
                    MMA_BF16(sacc[mt][nt], qa_l[mt], b0h, b1h);
                }
            }
        }

        // ---- causal mask (diagonal tile only)
        if (kt == qt) {
            #pragma unroll
            for (int mt = 0; mt < 2; mt++)
                #pragma unroll
                for (int nt = 0; nt < 8; nt++)
                    #pragma unroll
                    for (int cc = 0; cc < 4; cc++) {
                        int rloc = rtile + mt * 16 + (lane >> 2) + ((cc >= 2) ? 8 : 0);
                        int cloc = nt * 8 + (lane & 3) * 2 + (cc & 1);
                        if (cloc > rloc) sacc[mt][nt][cc] = -1e30f;
                    }
        }

        // ---- online softmax (per-row; rows split across 4-lane groups)
        #pragma unroll
        for (int mt = 0; mt < 2; mt++) {
            float mx0 = -1e30f, mx1 = -1e30f;
            #pragma unroll
            for (int nt = 0; nt < 8; nt++) {
                mx0 = fmaxf(mx0, fmaxf(sacc[mt][nt][0], sacc[mt][nt][1]));
                mx1 = fmaxf(mx1, fmaxf(sacc[mt][nt][2], sacc[mt][nt][3]));
            }
            mx0 = fmaxf(mx0, __shfl_xor_sync(0xffffffffu, mx0, 1));
            mx0 = fmaxf(mx0, __shfl_xor_sync(0xffffffffu, mx0, 2));
            mx1 = fmaxf(mx1, __shfl_xor_sync(0xffffffffu, mx1, 1));
            mx1 = fmaxf(mx1, __shfl_xor_sync(0xffffffffu, mx1, 2));
            float mn0 = fmaxf(m_r[mt][0], mx0);
            float mn1 = fmaxf(m_r[mt][1], mx1);
            float sc0 = fast_exp(m_r[mt][0] - mn0);
            float sc1 = fast_exp(m_r[mt][1] - mn1);
            m_r[mt][0] = mn0; m_r[mt][1] = mn1;
            float sum0 = 0.f, sum1 = 0.f;
            #pragma unroll
            for (int nt = 0; nt < 8; nt++) {
                float p0 = fast_exp(sacc[mt][nt][0] - mn0);
                float p1 = fast_exp(sacc[mt][nt][1] - mn0);
                float p2 = fast_exp(sacc[mt][nt][2] - mn1);
                float p3 = fast_exp(sacc[mt][nt][3] - mn1);
                sacc[mt][nt][0] = p0; sacc[mt][nt][1] = p1;
                sacc[mt][nt][2] = p2; sacc[mt][nt][3] = p3;
                sum0 += p0 + p1; sum1 += p2 + p3;
                oacc[mt][nt][0] *= sc0; oacc[mt][nt][1] *= sc0;
                oacc[mt][nt][2] *= sc1; oacc[mt][nt][3] *= sc1;
            }
            l_r[mt][0] = l_r[mt][0] * sc0 + sum0;   // per-lane partial
            l_r[mt][1] = l_r[mt][1] * sc1 + sum1;
        }

        // ---- O += P V (3-term split; P frags built in-register)
        #pragma unroll
        for (int j = 0; j < 4; j++) {
            uint32_t vb_h[4][4], vb_l[4][4];
            #pragma unroll
            for (int p = 0; p < 4; p++) {
                int row = p * 16 + (lane & 7) + ((lane >> 4) << 3);
                int col = j * 16 + (((lane >> 3) & 1) << 3);
                uint32_t off = (uint32_t)(row * QST + col) * 2;
                LDSM4(vb_h[p], Vh_o + off);
                LDSM4(vb_l[p], Vl_o + off);
            }
            #pragma unroll
            for (int mt = 0; mt < 2; mt++) {
                uint32_t ah[4], al[4];
                #pragma unroll
                for (int q = 0; q < 4; q++) {
                    int nt = 2 * j + (q >> 1);
                    float v0 = sacc[mt][nt][(q & 1) * 2];
                    float v1 = sacc[mt][nt][(q & 1) * 2 + 1];
                    uint32_t ph = pack_bf16(v0, v1);
                    float r0 = v0 - __uint_as_float(ph << 16);
                    float r1 = v1 - __uint_as_float(ph & 0xFFFF0000u);
                    ah[q] = ph;
                    al[q] = pack_bf16(r0, r1);
                }
                #pragma unroll
                for (int nt = 0; nt < 8; nt++) {
                    uint32_t b0h = vb_h[nt >> 1][(nt & 1) * 2];
                    uint32_t b1h = vb_h[nt >> 1][(nt & 1) * 2 + 1];
                    uint32_t b0l = vb_l[nt >> 1][(nt & 1) * 2];
                    uint32_t b1l = vb_l[nt >> 1][(nt & 1) * 2 + 1];
                    MMA_BF16(oacc[mt][nt], ah, b0h, b1h);
                    MMA_BF16(oacc[mt][nt], ah, b0l, b1l);
                    MMA_BF16(oacc[mt][nt], al, b0h, b1h);
                }
            }
        }
        __syncthreads();   // protect K/V smem for next iteration
    }

    // ---- epilogue: finish l reduction, normalize, write bf16 hi/lo
    #pragma unroll
    for (int mt = 0; mt < 2; mt++) {
        l_r[mt][0] += __shfl_xor_sync(0xffffffffu, l_r[mt][0], 1);
        l_r[mt][0] += __shfl_xor_sync(0xffffffffu, l_r[mt][0], 2);
        l_r[mt][1] += __shfl_xor_sync(0xffffffffu, l_r[mt][1], 1);
        l_r[mt][1] += __shfl_xor_sync(0xffffffffu, l_r[mt][1], 2);
        float inv0 = 1.0f / l_r[mt][0];
        float inv1 = 1.0f / l_r[mt][1];
        int tok = qt * 64 + rtile + mt * 16 + (lane >> 2);
        int colb = (kvh * 4 + hloc) * 64 + (lane & 3) * 2;
        #pragma unroll
        for (int nt = 0; nt < 8; nt++) {
            size_t o0 = (size_t)(b * SS + tok) * QDIM + colb + nt * 8;
            size_t o1 = o0 + (size_t)8 * QDIM;
            float v0 = oacc[mt][nt][0] * inv0, v1 = oacc[mt][nt][1] * inv0;
            float v2 = oacc[mt][nt][2] * inv1, v3 = oacc[mt][nt][3] * inv1;
            uint32_t h01 = pack_bf16(v0, v1);
            uint32_t h23 = pack_bf16(v2, v3);
            *(uint32_t*)&aoh[o0] = h01;
            *(uint32_t*)&aoh[o1] = h23;
            float r0 = v0 - __uint_as_float(h01 << 16);
            float r1 = v1 - __uint_as_float(h01 & 0xFFFF0000u);
            float r2 = v2 - __uint_as_float(h23 << 16);
            float r3 = v3 - __uint_as_float(h23 & 0xFFFF0000u);
            *(uint32_t*)&aol[o0] = pack_bf16(r0, r1);
            *(uint32_t*)&aol[o1] = pack_bf16(r2, r3);
        }
    }
}

// ---------------------------------------------------------------------------
extern "C" void kernel_launch(void* const* d_in, const int* in_sizes, int n_in,
                              void* d_out, int out_size)
{
    (void)in_sizes; (void)n_in; (void)out_size;
    const float* hs  = (const float*)d_in[0];
    const int*   pos = (const int*)d_in[2];
    const float* Wq  = (const float*)d_in[3];
    const float* Wk  = (const float*)d_in[4];
    const float* Wv  = (const float*)d_in[5];
    const float* Wo  = (const float*)d_in[6];
    float* out = (float*)d_out;

    float* qkvb;
    cudaGetSymbolAddress((void**)&qkvb, g_qkv);
    __nv_bfloat16 *hsh, *hsl, *qh, *ql, *kh, *kl, *vth, *vtl, *aoh, *aol;
    __nv_bfloat16 *wh, *wl, *woh, *wol;
    cudaGetSymbolAddress((void**)&hsh, g_hs_hi);
    cudaGetSymbolAddress((void**)&hsl, g_hs_lo);
    cudaGetSymbolAddress((void**)&qh, g_qh);
    cudaGetSymbolAddress((void**)&ql, g_ql);
    cudaGetSymbolAddress((void**)&kh, g_kh);
    cudaGetSymbolAddress((void**)&kl, g_kl);
    cudaGetSymbolAddress((void**)&vth, g_vth);
    cudaGetSymbolAddress((void**)&vtl, g_vtl);
    cudaGetSymbolAddress((void**)&aoh, g_aoh);
    cudaGetSymbolAddress((void**)&aol, g_aol);
    cudaGetSymbolAddress((void**)&wh, g_wqkvT_hi);
    cudaGetSymbolAddress((void**)&wl, g_wqkvT_lo);
    cudaGetSymbolAddress((void**)&woh, g_woT_hi);
    cudaGetSymbolAddress((void**)&wol, g_woT_lo);

    const int M = MTOT;
    cudaFuncSetAttribute(hmma_gemm, cudaFuncAttributeMaxDynamicSharedMemorySize, GEMM_SMEM);
    cudaFuncSetAttribute(attn_hmma, cudaFuncAttributeMaxDynamicSharedMemorySize, ATT_SMEM);

    // 1. split hidden states
    split_kernel<<<(M * DIN / 4 + 255) / 256, 256>>>(hs, hsh, hsl, M * DIN / 4);
    // 2. transpose+split fused QKV weights
    transpose_split_qkv<<<dim3(QKVN / 32, DIN / 32), dim3(32, 8)>>>(Wq, Wk, Wv, wh, wl);
    // 3. fused QKV projection
    hmma_gemm<<<dim3(QKVN / 128, M / 128), 256, GEMM_SMEM>>>(hsh, hsl, wh, wl, qkvb, M, QKVN, DIN);
    // 4. RoPE + split Q,K
    rope_split<<<(M * (NH + NKV) * 32 + 255) / 256, 256>>>(qkvb, pos, qh, ql, kh, kl);
    // 5. V split+transpose
    vsplit_t<<<dim3(SS / 32, HD / 32, BB * NKV), dim3(32, 8)>>>(qkvb, vth, vtl);
    // 6. attention (profiled by ncu -s 5 -c 1)
    attn_hmma<<<dim3(SS / 64, NKV, BB), 256, ATT_SMEM>>>(qh, ql, kh, kl, vth, vtl, aoh, aol);
    // 7. transpose+split Wo
    transpose_split_kernel<<<dim3(DOUT / 32, QDIM / 32), dim3(32, 8)>>>(Wo, woh, wol, QDIM, DOUT);
    // 8. output projection
    hmma_gemm<<<dim3(DOUT / 128, M / 128), 256, GEMM_SMEM>>>(aoh, aol, woh, wol, out, M, DOUT, QDIM);
}

// round 6
// speedup vs baseline: 3.2629x; 1.0225x over previous
#include <cuda_runtime.h>
#include <cuda_bf16.h>
#include <math.h>
#include <stdint.h>

#define BB 2
#define SS 2048
#define DIN 4096
#define NH 32
#define NKV 8
#define HD 64
#define QDIM 2048
#define KVDIM 512
#define QKVN 3072
#define DOUT 2048
#define MTOT 4096

// ---------------- scratch (__device__ globals) ------------------------------
__device__ __nv_bfloat16 g_hs_hi[MTOT*DIN];
__device__ __nv_bfloat16 g_hs_lo[MTOT*DIN];
__device__ __nv_bfloat16 g_qh[MTOT*QDIM];          // roped, pre-scaled Q hi/lo
__device__ __nv_bfloat16 g_ql[MTOT*QDIM];
__device__ __nv_bfloat16 g_kh[MTOT*KVDIM];         // roped K hi/lo
__device__ __nv_bfloat16 g_kl[MTOT*KVDIM];
__device__ __nv_bfloat16 g_vh[MTOT*KVDIM];         // V hi/lo (row-major)
__device__ __nv_bfloat16 g_vl[MTOT*KVDIM];
__device__ __nv_bfloat16 g_aoh[MTOT*QDIM];         // attention out hi/lo
__device__ __nv_bfloat16 g_aol[MTOT*QDIM];
__device__ __nv_bfloat16 g_wqkvT_hi[QKVN*DIN];
__device__ __nv_bfloat16 g_wqkvT_lo[QKVN*DIN];
__device__ __nv_bfloat16 g_woT_hi[DOUT*QDIM];
__device__ __nv_bfloat16 g_woT_lo[DOUT*QDIM];

// ---------------- helpers ----------------------------------------------------
__device__ __forceinline__ uint32_t smem_u32(const void* p) {
    uint32_t a;
    asm("{ .reg .u64 t; cvta.to.shared.u64 t, %1; cvt.u32.u64 %0, t; }" : "=r"(a) : "l"(p));
    return a;
}

#define LDSM4(r, addr)                                                           \
    asm volatile("ldmatrix.sync.aligned.m8n8.x4.shared.b16 {%0,%1,%2,%3}, [%4];" \
        : "=r"((r)[0]), "=r"((r)[1]), "=r"((r)[2]), "=r"((r)[3]) : "r"(addr))

#define LDSM4T(r, addr)                                                          \
    asm volatile("ldmatrix.sync.aligned.m8n8.x4.trans.shared.b16 {%0,%1,%2,%3}, [%4];" \
        : "=r"((r)[0]), "=r"((r)[1]), "=r"((r)[2]), "=r"((r)[3]) : "r"(addr))

#define MMA_BF16(d, a, b0, b1)                                                   \
    asm volatile("mma.sync.aligned.m16n8k16.row.col.f32.bf16.bf16.f32 "          \
        "{%0,%1,%2,%3}, {%4,%5,%6,%7}, {%8,%9}, {%0,%1,%2,%3};"                  \
        : "+f"((d)[0]), "+f"((d)[1]), "+f"((d)[2]), "+f"((d)[3])                 \
        : "r"((a)[0]), "r"((a)[1]), "r"((a)[2]), "r"((a)[3]), "r"(b0), "r"(b1))

#define CP_ASYNC16(dst, src)                                                     \
    asm volatile("cp.async.cg.shared.global [%0], [%1], 16;" :: "r"(dst), "l"(src) : "memory")
#define CP_COMMIT()  asm volatile("cp.async.commit_group;" ::: "memory")
#define CP_WAIT1()   asm volatile("cp.async.wait_group 1;" ::: "memory")
#define CP_WAIT0()   asm volatile("cp.async.wait_group 0;" ::: "memory")

// pack two fp32 -> bf16x2 (first arg -> low half)
__device__ __forceinline__ uint32_t pack_bf16(float lo, float hi) {
    uint32_t r;
    asm("cvt.rn.bf16x2.f32 %0, %1, %2;" : "=r"(r) : "f"(hi), "f"(lo));
    return r;
}
__device__ __forceinline__ float bfr(float x) {
    return __bfloat162float(__float2bfloat16(x));
}

// fast exp on the FMA pipe
__device__ __forceinline__ float fast_exp(float x) {
    float t = fmaxf(x * 1.4426950408889634f, -126.0f);
    float fi = floorf(t);
    float f = t - fi;
    float p = 1.54035304e-4f;
    p = fmaf(p, f, 1.33335581e-3f);
    p = fmaf(p, f, 9.61812911e-3f);
    p = fmaf(p, f, 5.55041087e-2f);
    p = fmaf(p, f, 2.40226507e-1f);
    p = fmaf(p, f, 6.93147181e-1f);
    p = fmaf(p, f, 1.0f);
    return p * __uint_as_float(((uint32_t)((int)fi + 127)) << 23);
}

// ---------------- prep kernels ------------------------------------------------
__global__ void split_kernel(const float* __restrict__ x, __nv_bfloat16* __restrict__ hi,
                             __nv_bfloat16* __restrict__ lo, int n4) {
    int i = blockIdx.x * blockDim.x + threadIdx.x;
    if (i >= n4) return;
    float4 v = ((const float4*)x)[i];
    __nv_bfloat16 h[4], l[4];
    float vv[4] = {v.x, v.y, v.z, v.w};
    #pragma unroll
    for (int j = 0; j < 4; j++) {
        h[j] = __float2bfloat16(vv[j]);
        l[j] = __float2bfloat16(vv[j] - __bfloat162float(h[j]));
    }
    ((uint2*)hi)[i] = *(uint2*)h;
    ((uint2*)lo)[i] = *(uint2*)l;
}

__global__ void transpose_split_qkv(const float* __restrict__ Wq, const float* __restrict__ Wk,
                                    const float* __restrict__ Wv,
                                    __nv_bfloat16* __restrict__ Th, __nv_bfloat16* __restrict__ Tl) {
    __shared__ float t[32][33];
    int n0 = blockIdx.x * 32;
    int k0 = blockIdx.y * 32;
    const float* W; int srcN, sn0;
    if (n0 < QDIM)              { W = Wq; srcN = QDIM;  sn0 = n0; }
    else if (n0 < QDIM + KVDIM) { W = Wk; srcN = KVDIM; sn0 = n0 - QDIM; }
    else                        { W = Wv; srcN = KVDIM; sn0 = n0 - QDIM - KVDIM; }
    int x = threadIdx.x, y = threadIdx.y;
    #pragma unroll
    for (int i = 0; i < 32; i += 8)
        t[y + i][x] = W[(size_t)(k0 + y + i) * srcN + sn0 + x];
    __syncthreads();
    #pragma unroll
    for (int i = 0; i < 32; i += 8) {
        float v = t[x][y + i];
        float h = bfr(v);
        size_t idx = (size_t)(n0 + y + i) * DIN + k0 + x;
        Th[idx] = __float2bfloat16(h);
        Tl[idx] = __float2bfloat16(v - h);
    }
}

__global__ void transpose_split_kernel(const float* __restrict__ W,
                                       __nv_bfloat16* __restrict__ Th,
                                       __nv_bfloat16* __restrict__ Tl, int K, int N) {
    __shared__ float t[32][33];
    int k0 = blockIdx.y * 32, n0 = blockIdx.x * 32;
    int x = threadIdx.x, y = threadIdx.y;
    #pragma unroll
    for (int i = 0; i < 32; i += 8)
        t[y + i][x] = W[(size_t)(k0 + y + i) * N + n0 + x];
    __syncthreads();
    #pragma unroll
    for (int i = 0; i < 32; i += 8) {
        float v = t[x][y + i];
        float h = bfr(v);
        size_t idx = (size_t)(n0 + y + i) * K + k0 + x;
        Th[idx] = __float2bfloat16(h);
        Tl[idx] = __float2bfloat16(v - h);
    }
}

// ---------------- split-bf16 HMMA GEMM core (3-stage) --------------------------
#define AST 40
#define TILE_E (128*AST)
#define STAGE_E (4*TILE_E)
#define NSTAGE 3
#define GEMM_SMEM (NSTAGE * STAGE_E * 2)

__device__ __forceinline__ void load_stage(
    uint32_t sbase_bytes, int tid, int bm, int bn, int k0, int K,
    const __nv_bfloat16* __restrict__ Ah, const __nv_bfloat16* __restrict__ Al,
    const __nv_bfloat16* __restrict__ Bh, const __nv_bfloat16* __restrict__ Bl)
{
    #pragma unroll
    for (int i = 0; i < 8; i++) {
        int cid = tid + i * 256;
        int arr = cid >> 9;
        int rem = cid & 511;
        int row = rem >> 2;
        int c16 = rem & 3;
        const __nv_bfloat16* g;
        if (arr == 0)      g = Ah + (size_t)(bm + row) * K + k0 + c16 * 8;
        else if (arr == 1) g = Al + (size_t)(bm + row) * K + k0 + c16 * 8;
        else if (arr == 2) g = Bh + (size_t)(bn + row) * K + k0 + c16 * 8;
        else               g = Bl + (size_t)(bn + row) * K + k0 + c16 * 8;
        uint32_t d = sbase_bytes + (uint32_t)(arr * TILE_E + row * AST + c16 * 8) * 2;
        CP_ASYNC16(d, g);
    }
    CP_COMMIT();
}

__device__ __forceinline__ void gemm_mainloop(
    float acc[2][8][4], uint32_t smb, int tid, int bm, int bn, int K,
    const __nv_bfloat16* __restrict__ Ah, const __nv_bfloat16* __restrict__ Al,
    const __nv_bfloat16* __restrict__ Bh, const __nv_bfloat16* __restrict__ Bl)
{
    const int wid = tid >> 5;
    const int lane = tid & 31;
    const int wm = (wid & 3) * 32;
    const int wn = (wid >> 2) * 64;
    const int nch = K >> 5;

    load_stage(smb, tid, bm, bn, 0, K, Ah, Al, Bh, Bl);
    load_stage(smb + STAGE_E * 2, tid, bm, bn, 32, K, Ah, Al, Bh, Bl);

    int st = 0, pst = 2;
    for (int c = 0; c < nch; c++) {
        CP_WAIT1();
        __syncthreads();

        if (c + 2 < nch)
            load_stage(smb + (uint32_t)pst * STAGE_E * 2, tid, bm, bn,
                       (c + 2) << 5, K, Ah, Al, Bh, Bl);

        uint32_t Ab  = smb + (uint32_t)st * STAGE_E * 2;
        uint32_t Alb = Ab + TILE_E * 2;
        uint32_t Bb  = Ab + 2 * TILE_E * 2;
        uint32_t Blb = Ab + 3 * TILE_E * 2;

        #pragma unroll
        for (int ks = 0; ks < 2; ks++) {
            uint32_t ah[2][4], al[2][4], bh[4][4], bl[4][4];
            #pragma unroll
            for (int mt = 0; mt < 2; mt++) {
                int row = wm + mt * 16 + (lane & 15);
                int col = ks * 16 + ((lane >> 4) << 3);
                uint32_t off = (uint32_t)(row * AST + col) * 2;
                LDSM4(ah[mt], Ab + off);
                LDSM4(al[mt], Alb + off);
            }
            #pragma unroll
            for (int p = 0; p < 4; p++) {
                int row = wn + p * 16 + (lane & 7) + ((lane >> 4) << 3);
                int col = ks * 16 + (((lane >> 3) & 1) << 3);
                uint32_t off = (uint32_t)(row * AST + col) * 2;
                LDSM4(bh[p], Bb + off);
                LDSM4(bl[p], Blb + off);
            }
            #pragma unroll
            for (int mt = 0; mt < 2; mt++) {
                #pragma unroll
                for (int nt = 0; nt < 8; nt++) {
                    uint32_t b0h = bh[nt >> 1][(nt & 1) * 2];
                    uint32_t b1h = bh[nt >> 1][(nt & 1) * 2 + 1];
                    uint32_t b0l = bl[nt >> 1][(nt & 1) * 2];
                    uint32_t b1l = bl[nt >> 1][(nt & 1) * 2 + 1];
                    MMA_BF16(acc[mt][nt], ah[mt], b0h, b1h);
                    MMA_BF16(acc[mt][nt], ah[mt], b0l, b1l);
                    MMA_BF16(acc[mt][nt], al[mt], b0h, b1h);
                }
            }
        }
        st = (st == 2) ? 0 : st + 1;
        pst = (pst == 2) ? 0 : pst + 1;
    }
}

// GEMM with plain fp32 C output (O projection)
__global__ __launch_bounds__(256, 1)
void hmma_gemm_c(const __nv_bfloat16* __restrict__ Ah, const __nv_bfloat16* __restrict__ Al,
                 const __nv_bfloat16* __restrict__ Bh, const __nv_bfloat16* __restrict__ Bl,
                 float* __restrict__ C, int M, int N, int K)
{
    extern __shared__ __nv_bfloat16 sm[];
    const int tid = threadIdx.x;
    const int wid = tid >> 5, lane = tid & 31;
    const int bm = blockIdx.y * 128, bn = blockIdx.x * 128;
    const int wm = (wid & 3) * 32, wn = (wid >> 2) * 64;

    float acc[2][8][4];
    #pragma unroll
    for (int mt = 0; mt < 2; mt++)
        #pragma unroll
        for (int nt = 0; nt < 8; nt++)
            #pragma unroll
            for (int j = 0; j < 4; j++) acc[mt][nt][j] = 0.f;

    gemm_mainloop(acc, smem_u32(sm), tid, bm, bn, K, Ah, Al, Bh, Bl);

    #pragma unroll
    for (int mt = 0; mt < 2; mt++)
        #pragma unroll
        for (int nt = 0; nt < 8; nt++) {
            int r0  = bm + wm + mt * 16 + (lane >> 2);
            int col = bn + wn + nt * 8 + (lane & 3) * 2;
            *(float2*)&C[(size_t)r0 * N + col] = make_float2(acc[mt][nt][0], acc[mt][nt][1]);
            *(float2*)&C[(size_t)(r0 + 8) * N + col] = make_float2(acc[mt][nt][2], acc[mt][nt][3]);
        }
}

// QKV GEMM with fused RoPE + hi/lo-split epilogue
__global__ __launch_bounds__(256, 1)
void hmma_gemm_qkv(const __nv_bfloat16* __restrict__ Ah, const __nv_bfloat16* __restrict__ Al,
                   const __nv_bfloat16* __restrict__ Bh, const __nv_bfloat16* __restrict__ Bl,
                   const int* __restrict__ pos,
                   __nv_bfloat16* __restrict__ qh, __nv_bfloat16* __restrict__ ql,
                   __nv_bfloat16* __restrict__ kh, __nv_bfloat16* __restrict__ kl,
                   __nv_bfloat16* __restrict__ vh, __nv_bfloat16* __restrict__ vl)
{
    extern __shared__ __nv_bfloat16 sm[];
    const int tid = threadIdx.x;
    const int wid = tid >> 5, lane = tid & 31;
    const int bm = blockIdx.y * 128, bn = blockIdx.x * 128;
    const int wm = (wid & 3) * 32, wn = (wid >> 2) * 64;

    float acc[2][8][4];
    #pragma unroll
    for (int mt = 0; mt < 2; mt++)
        #pragma unroll
        for (int nt = 0; nt < 8; nt++)
            #pragma unroll
            for (int j = 0; j < 4; j++) acc[mt][nt][j] = 0.f;

    gemm_mainloop(acc, smem_u32(sm), tid, bm, bn, DIN, Ah, Al, Bh, Bl);

    const int ncol0 = bn + wn;   // 64-aligned -> exactly one head per warp
    if (ncol0 >= QDIM + KVDIM) {
        // ---- V: plain split, row-major
        int colb = ncol0 - (QDIM + KVDIM) + (lane & 3) * 2;
        #pragma unroll
        for (int mt = 0; mt < 2; mt++)
            #pragma unroll
            for (int nt = 0; nt < 8; nt++)
                #pragma unroll
                for (int rs = 0; rs < 2; rs++) {
                    int m = bm + wm + mt * 16 + (lane >> 2) + rs * 8;
                    float v0 = acc[mt][nt][rs * 2], v1 = acc[mt][nt][rs * 2 + 1];
                    float h0 = bfr(v0), h1 = bfr(v1);
                    size_t o = (size_t)m * KVDIM + colb + nt * 8;
                    *(uint32_t*)&vh[o] = pack_bf16(h0, h1);
                    *(uint32_t*)&vl[o] = pack_bf16(v0 - h0, v1 - h1);
                }
    } else {
        // ---- Q or K: RoPE on (jp, jp+32) pairs held by octets (nt, nt+4)
        const int isQ = ncol0 < QDIM;
        const float scale = isQ ? 0.125f : 1.0f;
        __nv_bfloat16* oh = isQ ? qh : kh;
        __nv_bfloat16* ol = isQ ? ql : kl;
        const int stride = isQ ? QDIM : KVDIM;
        const int colbase = isQ ? ncol0 : ncol0 - QDIM;
        #pragma unroll
        for (int mt = 0; mt < 2; mt++)
            #pragma unroll
            for (int rs = 0; rs < 2; rs++) {
                int m = bm + wm + mt * 16 + (lane >> 2) + rs * 8;
                float pf = (float)pos[m];
                #pragma unroll
                for (int nt = 0; nt < 4; nt++) {
                    int jp0 = nt * 8 + (lane & 3) * 2;
                    float y1[2], y2[2];
                    #pragma unroll
                    for (int c = 0; c < 2; c++) {
                        float inv = exp2f(-(float)(jp0 + c) * (13.287712379549449f / 32.0f));
                        float ang = pf * inv;
                        float s, cs;
                        sincosf(ang, &s, &cs);
                        float v1 = acc[mt][nt][rs * 2 + c];
                        float v2 = acc[mt][nt + 4][rs * 2 + c];
                        y1[c] = (v1 * cs - v2 * s) * scale;
                        y2[c] = (v2 * cs + v1 * s) * scale;
                    }
                    size_t o = (size_t)m * stride + colbase + jp0;
                    float h10 = bfr(y1[0]), h11 = bfr(y1[1]);
                    float h20 = bfr(y2[0]), h21 = bfr(y2[1]);
                    *(uint32_t*)&oh[o]      = pack_bf16(h10, h11);
                    *(uint32_t*)&ol[o]      = pack_bf16(y1[0] - h10, y1[1] - h11);
                    *(uint32_t*)&oh[o + 32] = pack_bf16(h20, h21);
                    *(uint32_t*)&ol[o + 32] = pack_bf16(y2[0] - h20, y2[1] - h21);
                }
            }
    }
}

// ---------------- HMMA flash attention (triple-buffered K/V) -------------------
#define QST 72
#define ATT_Q_E  (256*QST)
#define ATT_KV_E (64*QST)
#define ATT_KV_STAGE (4*ATT_KV_E*2)
#define ATT_QBYTES (2*ATT_Q_E*2)
#define ATT_SMEM (ATT_QBYTES + 3*ATT_KV_STAGE)   // 184320 bytes

__device__ __forceinline__ void attn_load_kv(
    uint32_t stage_base, int tid, int b, int kvh, int kt,
    const __nv_bfloat16* __restrict__ kh, const __nv_bfloat16* __restrict__ kl,
    const __nv_bfloat16* __restrict__ vh, const __nv_bfloat16* __restrict__ vl)
{
    #pragma unroll
    for (int it = 0; it < 8; it++) {
        int cid = tid + it * 256;
        int arr = cid >> 9;
        int rem = cid & 511;
        int row = rem >> 3;
        int c   = rem & 7;
        const __nv_bfloat16* base = (arr == 0) ? kh : (arr == 1) ? kl : (arr == 2) ? vh : vl;
        const __nv_bfloat16* src = base + (size_t)(b * SS + kt * 64 + row) * KVDIM + kvh * 64 + c * 8;
        CP_ASYNC16(stage_base + (uint32_t)arr * ATT_KV_E * 2 + (uint32_t)(row * QST + c * 8) * 2, src);
    }
    CP_COMMIT();
}

__global__ __launch_bounds__(256, 1)
void attn_hmma(const __nv_bfloat16* __restrict__ qh, const __nv_bfloat16* __restrict__ ql,
               const __nv_bfloat16* __restrict__ kh, const __nv_bfloat16* __restrict__ kl,
               const __nv_bfloat16* __restrict__ vh, const __nv_bfloat16* __restrict__ vl,
               __nv_bfloat16* __restrict__ aoh, __nv_bfloat16* __restrict__ aol)
{
    extern __shared__ __nv_bfloat16 smatt[];
    const int qt  = gridDim.x - 1 - blockIdx.x;
    const int kvh = blockIdx.y;
    const int b   = blockIdx.z;
    const int tid = threadIdx.x, wid = tid >> 5, lane = tid & 31;

    const uint32_t smb  = smem_u32(smatt);
    const uint32_t Qh_o = smb;
    const uint32_t Ql_o = smb + ATT_Q_E * 2;

    // ---- Q tile load (group 0)
    #pragma unroll
    for (int it = 0; it < 16; it++) {
        int cid = tid + it * 256;
        int arr = cid >> 11;
        int rem = cid & 2047;
        int row = rem >> 3;
        int c   = rem & 7;
        const __nv_bfloat16* src = (arr ? ql : qh)
            + (size_t)(b * SS + qt * 64 + (row & 63)) * QDIM
            + (kvh * 4 + (row >> 6)) * 64 + c * 8;
        CP_ASYNC16((arr ? Ql_o : Qh_o) + (uint32_t)(row * QST + c * 8) * 2, src);
    }
    CP_COMMIT();

    // prefetch kt=0 and (if any) kt=1
    attn_load_kv(smb + ATT_QBYTES, tid, b, kvh, 0, kh, kl, vh, vl);
    if (qt >= 1)
        attn_load_kv(smb + ATT_QBYTES + ATT_KV_STAGE, tid, b, kvh, 1, kh, kl, vh, vl);

    float m_r[2][2], l_r[2][2], oacc[2][8][4];
    #pragma unroll
    for (int mt = 0; mt < 2; mt++) {
        m_r[mt][0] = -1e30f; m_r[mt][1] = -1e30f;
        l_r[mt][0] = 0.f;    l_r[mt][1] = 0.f;
        #pragma unroll
        for (int nt = 0; nt < 8; nt++)
            #pragma unroll
            for (int j = 0; j < 4; j++) oacc[mt][nt][j] = 0.f;
    }

    const int wrow  = wid * 32;
    const int hloc  = wid >> 1;
    const int rtile = (wid & 1) * 32;

    int st = 0;
    for (int kt = 0; kt <= qt; kt++) {
        if (kt < qt) CP_WAIT1(); else CP_WAIT0();
        __syncthreads();

        if (kt + 2 <= qt)
            attn_load_kv(smb + ATT_QBYTES + (uint32_t)((kt + 2) % 3) * ATT_KV_STAGE,
                         tid, b, kvh, kt + 2, kh, kl, vh, vl);

        const uint32_t stg  = smb + ATT_QBYTES + (uint32_t)st * ATT_KV_STAGE;
        const uint32_t Kh_o = stg;
        const uint32_t Kl_o = stg + ATT_KV_E * 2;
        const uint32_t Vh_o = stg + 2 * ATT_KV_E * 2;
        const uint32_t Vl_o = stg + 3 * ATT_KV_E * 2;

        // ---- S = Q K^T
        float sacc[2][8][4];
        #pragma unroll
        for (int mt = 0; mt < 2; mt++)
            #pragma unroll
            for (int nt = 0; nt < 8; nt++)
                #pragma unroll
                for (int j = 0; j < 4; j++) sacc[mt][nt][j] = 0.f;

        #pragma unroll
        for (int ks = 0; ks < 4; ks++) {
            uint32_t qa_h[2][4], qa_l[2][4], kb_h[4][4], kb_l[4][4];
            #pragma unroll
            for (int mt = 0; mt < 2; mt++) {
                int row = wrow + mt * 16 + (lane & 15);
                int col = ks * 16 + ((lane >> 4) << 3);
                uint32_t off = (uint32_t)(row * QST + col) * 2;
                LDSM4(qa_h[mt], Qh_o + off);
                LDSM4(qa_l[mt], Ql_o + off);
            }
            #pragma unroll
            for (int p = 0; p < 4; p++) {
                int row = p * 16 + (lane & 7) + ((lane >> 4) << 3);
                int col = ks * 16 + (((lane >> 3) & 1) << 3);
                uint32_t off = (uint32_t)(row * QST + col) * 2;
                LDSM4(kb_h[p], Kh_o + off);
                LDSM4(kb_l[p], Kl_o + off);
            }
            #pragma unroll
            for (int mt = 0; mt < 2; mt++) {
                #pragma unroll
                for (int nt = 0; nt < 8; nt++) {
                    uint32_t b0h = kb_h[nt >> 1][(nt & 1) * 2];
                    uint32_t b1h = kb_h[nt >> 1][(nt & 1) * 2 + 1];
                    uint32_t b0l = kb_l[nt >> 1][(nt & 1) * 2];
                    uint32_t b1l = kb_l[nt >> 1][(nt & 1) * 2 + 1];
                    MMA_BF16(sacc[mt][nt], qa_h[mt], b0h, b1h);
                    MMA_BF16(sacc[mt][nt], qa_h[mt], b0l, b1l);
                    MMA_BF16(sacc[mt][nt], qa_l[mt], b0h, b1h);
                }
            }
        }

        if (kt == qt) {
            #pragma unroll
            for (int mt = 0; mt < 2; mt++)
                #pragma unroll
                for (int nt = 0; nt < 8; nt++)
                    #pragma unroll
                    for (int cc = 0; cc < 4; cc++) {
                        int rloc = rtile + mt * 16 + (lane >> 2) + ((cc >= 2) ? 8 : 0);
                        int cloc = nt * 8 + (lane & 3) * 2 + (cc & 1);
                        if (cloc > rloc) sacc[mt][nt][cc] = -1e30f;
                    }
        }

        // ---- online softmax
        #pragma unroll
        for (int mt = 0; mt < 2; mt++) {
            float mx0 = -1e30f, mx1 = -1e30f;
            #pragma unroll
            for (int nt = 0; nt < 8; nt++) {
                mx0 = fmaxf(mx0, fmaxf(sacc[mt][nt][0], sacc[mt][nt][1]));
                mx1 = fmaxf(mx1, fmaxf(sacc[mt][nt][2], sacc[mt][nt][3]));
            }
            mx0 = fmaxf(mx0, __shfl_xor_sync(0xffffffffu, mx0, 1));
            mx0 = fmaxf(mx0, __shfl_xor_sync(0xffffffffu, mx0, 2));
            mx1 = fmaxf(mx1, __shfl_xor_sync(0xffffffffu, mx1, 1));
            mx1 = fmaxf(mx1, __shfl_xor_sync(0xffffffffu, mx1, 2));
            float mn0 = fmaxf(m_r[mt][0], mx0);
            float mn1 = fmaxf(m_r[mt][1], mx1);
            float sc0 = fast_exp(m_r[mt][0] - mn0);
            float sc1 = fast_exp(m_r[mt][1] - mn1);
            m_r[mt][0] = mn0; m_r[mt][1] = mn1;
            float sum0 = 0.f, sum1 = 0.f;
            #pragma unroll
            for (int nt = 0; nt < 8; nt++) {
                float p0 = fast_exp(sacc[mt][nt][0] - mn0);
                float p1 = fast_exp(sacc[mt][nt][1] - mn0);
                float p2 = fast_exp(sacc[mt][nt][2] - mn1);
                float p3 = fast_exp(sacc[mt][nt][3] - mn1);
                sacc[mt][nt][0] = p0; sacc[mt][nt][1] = p1;
                sacc[mt][nt][2] = p2; sacc[mt][nt][3] = p3;
                sum0 += p0 + p1; sum1 += p2 + p3;
                oacc[mt][nt][0] *= sc0; oacc[mt][nt][1] *= sc0;
                oacc[mt][nt][2] *= sc1; oacc[mt][nt][3] *= sc1;
            }
            l_r[mt][0] = l_r[mt][0] * sc0 + sum0;
            l_r[mt][1] = l_r[mt][1] * sc1 + sum1;
        }

        // ---- O += P V  (V row-major, fragments via ldmatrix.trans)
        #pragma unroll
        for (int j = 0; j < 4; j++) {        // k-steps over 16-token groups
            uint32_t vb_h[4][4], vb_l[4][4];
            int tok_off = (lane & 7) + (((lane >> 3) & 1) << 3);
            int d_off   = ((lane >> 4) & 1) << 3;
            #pragma unroll
            for (int p = 0; p < 4; p++) {    // d-groups of 16
                uint32_t off = (uint32_t)((j * 16 + tok_off) * QST + p * 16 + d_off) * 2;
                LDSM4T(vb_h[p], Vh_o + off);
                LDSM4T(vb_l[p], Vl_o + off);
            }
            #pragma unroll
            for (int mt = 0; mt < 2; mt++) {
                uint32_t ah[4], al[4];
                #pragma unroll
                for (int q = 0; q < 4; q++) {
                    int nt = 2 * j + (q >> 1);
                    float v0 = sacc[mt][nt][(q & 1) * 2];
                    float v1 = sacc[mt][nt][(q & 1) * 2 + 1];
                    uint32_t ph = pack_bf16(v0, v1);
                    float r0 = v0 - __uint_as_float(ph << 16);
                    float r1 = v1 - __uint_as_float(ph & 0xFFFF0000u);
                    ah[q] = ph;
                    al[q] = pack_bf16(r0, r1);
                }
                #pragma unroll
                for (int nt = 0; nt < 8; nt++) {
                    uint32_t b0h = vb_h[nt >> 1][(nt & 1) * 2];
                    uint32_t b1h = vb_h[nt >> 1][(nt & 1) * 2 + 1];
                    uint32_t b0l = vb_l[nt >> 1][(nt & 1) * 2];
                    uint32_t b1l = vb_l[nt >> 1][(nt & 1) * 2 + 1];
                    MMA_BF16(oacc[mt][nt], ah, b0h, b1h);
                    MMA_BF16(oacc[mt][nt], ah, b0l, b1l);
                    MMA_BF16(oacc[mt][nt], al, b0h, b1h);
                }
            }
        }
        st = (st == 2) ? 0 : st + 1;
    }

    // ---- epilogue
    #pragma unroll
    for (int mt = 0; mt < 2; mt++) {
        l_r[mt][0] += __shfl_xor_sync(0xffffffffu, l_r[mt][0], 1);
        l_r[mt][0] += __shfl_xor_sync(0xffffffffu, l_r[mt][0], 2);
        l_r[mt][1] += __shfl_xor_sync(0xffffffffu, l_r[mt][1], 1);
        l_r[mt][1] += __shfl_xor_sync(0xffffffffu, l_r[mt][1], 2);
        float inv0 = 1.0f / l_r[mt][0];
        float inv1 = 1.0f / l_r[mt][1];
        int tok = qt * 64 + rtile + mt * 16 + (lane >> 2);
        int colb = (kvh * 4 + hloc) * 64 + (lane & 3) * 2;
        #pragma unroll
        for (int nt = 0; nt < 8; nt++) {
            size_t o0 = (size_t)(b * SS + tok) * QDIM + colb + nt * 8;
            size_t o1 = o0 + (size_t)8 * QDIM;
            float v0 = oacc[mt][nt][0] * inv0, v1 = oacc[mt][nt][1] * inv0;
            float v2 = oacc[mt][nt][2] * inv1, v3 = oacc[mt][nt][3] * inv1;
            uint32_t h01 = pack_bf16(v0, v1);
            uint32_t h23 = pack_bf16(v2, v3);
            *(uint32_t*)&aoh[o0] = h01;
            *(uint32_t*)&aoh[o1] = h23;
            float r0 = v0 - __uint_as_float(h01 << 16);
            float r1 = v1 - __uint_as_float(h01 & 0xFFFF0000u);
            float r2 = v2 - __uint_as_float(h23 << 16);
            float r3 = v3 - __uint_as_float(h23 & 0xFFFF0000u);
            *(uint32_t*)&aol[o0] = pack_bf16(r0, r1);
            *(uint32_t*)&aol[o1] = pack_bf16(r2, r3);
        }
    }
}

// ---------------------------------------------------------------------------
extern "C" void kernel_launch(void* const* d_in, const int* in_sizes, int n_in,
                              void* d_out, int out_size)
{
    (void)in_sizes; (void)n_in; (void)out_size;
    const float* hs  = (const float*)d_in[0];
    const int*   pos = (const int*)d_in[2];
    const float* Wq  = (const float*)d_in[3];
    const float* Wk  = (const float*)d_in[4];
    const float* Wv  = (const float*)d_in[5];
    const float* Wo  = (const float*)d_in[6];
    float* out = (float*)d_out;

    __nv_bfloat16 *hsh, *hsl, *qh, *ql, *kh, *kl, *vh, *vl, *aoh, *aol;
    __nv_bfloat16 *wh, *wl, *woh, *wol;
    cudaGetSymbolAddress((void**)&hsh, g_hs_hi);
    cudaGetSymbolAddress((void**)&hsl, g_hs_lo);
    cudaGetSymbolAddress((void**)&qh, g_qh);
    cudaGetSymbolAddress((void**)&ql, g_ql);
    cudaGetSymbolAddress((void**)&kh, g_kh);
    cudaGetSymbolAddress((void**)&kl, g_kl);
    cudaGetSymbolAddress((void**)&vh, g_vh);
    cudaGetSymbolAddress((void**)&vl, g_vl);
    cudaGetSymbolAddress((void**)&aoh, g_aoh);
    cudaGetSymbolAddress((void**)&aol, g_aol);
    cudaGetSymbolAddress((void**)&wh, g_wqkvT_hi);
    cudaGetSymbolAddress((void**)&wl, g_wqkvT_lo);
    cudaGetSymbolAddress((void**)&woh, g_woT_hi);
    cudaGetSymbolAddress((void**)&wol, g_woT_lo);

    const int M = MTOT;
    cudaFuncSetAttribute(hmma_gemm_c,   cudaFuncAttributeMaxDynamicSharedMemorySize, GEMM_SMEM);
    cudaFuncSetAttribute(hmma_gemm_qkv, cudaFuncAttributeMaxDynamicSharedMemorySize, GEMM_SMEM);
    cudaFuncSetAttribute(attn_hmma,     cudaFuncAttributeMaxDynamicSharedMemorySize, ATT_SMEM);

    split_kernel<<<(M * DIN / 4 + 255) / 256, 256>>>(hs, hsh, hsl, M * DIN / 4);
    transpose_split_qkv<<<dim3(QKVN / 32, DIN / 32), dim3(32, 8)>>>(Wq, Wk, Wv, wh, wl);
    transpose_split_kernel<<<dim3(DOUT / 32, QDIM / 32), dim3(32, 8)>>>(Wo, woh, wol, QDIM, DOUT);
    hmma_gemm_qkv<<<dim3(QKVN / 128, M / 128), 256, GEMM_SMEM>>>(
        hsh, hsl, wh, wl, pos, qh, ql, kh, kl, vh, vl);
    attn_hmma<<<dim3(SS / 64, NKV, BB), 256, ATT_SMEM>>>(qh, ql, kh, kl, vh, vl, aoh, aol);
    hmma_gemm_c<<<dim3(DOUT / 128, M / 128), 256, GEMM_SMEM>>>(aoh, aol, woh, wol, out, M, DOUT, QDIM);
}